// round 4
// baseline (speedup 1.0000x reference)
#include <cuda_runtime.h>
#include <math.h>

// ---------------- problem constants ----------------
#define BATCH   16
#define SEQ     197
#define DIM     384
#define NLAYER  24
#define DIN     768
#define DST     16
#define DTRANK  24
#define NCLS    1000
#define MTOK    (BATCH*SEQ)       // 3152
#define NPATCH  196
#define MPATCH  (BATCH*NPATCH)    // 3136
#define KPATCH  768               // 3*16*16

// ---------------- device scratch (no cudaMalloc allowed) ----------------
__device__ float g_im2col[MPATCH*KPATCH];   // patch pixels
__device__ float g_hid[MTOK*DIM];           // mixer output / initial h
__device__ float g_res[MTOK*DIM];           // residual stream
__device__ float g_u[MTOK*DIM];             // LN output
__device__ float g_xz[MTOK*2*DIN];          // in_proj output (xc | z)
__device__ float g_xcs[MTOK*DIN];           // silu(conv(xc))
__device__ float g_dbl[MTOK*56];            // x_proj output (dt_r | B | C)
__device__ float g_dt[MTOK*DIN];            // softplus(dt)
__device__ float g_y[MTOK*DIN];             // scan+gate output (also reused as patch tokens)
__device__ float g_cls[BATCH*DIM];          // final LN'd cls tokens

// ---------------- generic NT SGEMM: C[m,n] = sum_k A[m,k]*B[n,k] (+bias)(+softplus) ----
// Requires K % 8 == 0, lda/ldb % 4 == 0 (true for every call site here).
// epi: 0 = none, 1 = +bias[n], 2 = softplus(x + bias[n])
__global__ void __launch_bounds__(256) gemm_nt(
    const float* __restrict__ A, int lda,
    const float* __restrict__ B, int ldb,
    float* __restrict__ C, int ldc,
    const float* __restrict__ bias,
    int M, int N, int K, int epi)
{
    __shared__ __align__(16) float As[8][132];
    __shared__ __align__(16) float Bs[8][132];

    const int tid = threadIdx.x;
    const int tx  = tid & 15;      // 16 thread cols
    const int ty  = tid >> 4;      // 16 thread rows
    const int row0 = blockIdx.y * 128;
    const int col0 = blockIdx.x * 128;

    // cooperative load mapping: 256 threads, 128 rows x 8 cols per operand tile
    const int lr = tid >> 1;           // 0..127
    const int lc = (tid & 1) << 2;     // 0 or 4

    float acc[8][8];
#pragma unroll
    for (int i = 0; i < 8; i++)
#pragma unroll
        for (int j = 0; j < 8; j++) acc[i][j] = 0.f;

    const int ar = row0 + lr;
    const int br = col0 + lr;
    const bool aval = (ar < M);
    const bool bval = (br < N);
    const float* Aptr = A + (size_t)ar * lda + lc;
    const float* Bptr = B + (size_t)br * ldb + lc;

    for (int k0 = 0; k0 < K; k0 += 8) {
        float4 av = make_float4(0.f, 0.f, 0.f, 0.f);
        float4 bv = make_float4(0.f, 0.f, 0.f, 0.f);
        if (aval) av = *(const float4*)(Aptr + k0);
        if (bval) bv = *(const float4*)(Bptr + k0);
        As[lc+0][lr] = av.x; As[lc+1][lr] = av.y; As[lc+2][lr] = av.z; As[lc+3][lr] = av.w;
        Bs[lc+0][lr] = bv.x; Bs[lc+1][lr] = bv.y; Bs[lc+2][lr] = bv.z; Bs[lc+3][lr] = bv.w;
        __syncthreads();
#pragma unroll
        for (int k = 0; k < 8; k++) {
            float4 a0 = *(const float4*)&As[k][ty*8];
            float4 a1 = *(const float4*)&As[k][ty*8+4];
            float4 b0 = *(const float4*)&Bs[k][tx*8];
            float4 b1 = *(const float4*)&Bs[k][tx*8+4];
            float ra[8] = {a0.x,a0.y,a0.z,a0.w,a1.x,a1.y,a1.z,a1.w};
            float rb[8] = {b0.x,b0.y,b0.z,b0.w,b1.x,b1.y,b1.z,b1.w};
#pragma unroll
            for (int i = 0; i < 8; i++)
#pragma unroll
                for (int j = 0; j < 8; j++)
                    acc[i][j] += ra[i]*rb[j];
        }
        __syncthreads();
    }

#pragma unroll
    for (int i = 0; i < 8; i++) {
        int r = row0 + ty*8 + i;
        if (r < M) {
#pragma unroll
            for (int j = 0; j < 8; j++) {
                int c = col0 + tx*8 + j;
                if (c < N) {
                    float v = acc[i][j];
                    if (epi) {
                        v += bias[c];
                        if (epi == 2) v = (v > 20.f) ? v : log1pf(expf(v));
                    }
                    C[(size_t)r*ldc + c] = v;
                }
            }
        }
    }
}

// ---------------- im2col for 16x16/stride16 patch conv ----------------
__global__ void im2col_kernel(const float* __restrict__ x) {
    int idx = blockIdx.x * blockDim.x + threadIdx.x;
    if (idx >= MPATCH*KPATCH) return;
    int m = idx / KPATCH, k = idx - m*KPATCH;
    int b = m / NPATCH,  p = m - b*NPATCH;
    int pr = p / 14, pc = p - pr*14;
    int c = k >> 8, r = k & 255;
    int i = r >> 4, j = r & 15;
    g_im2col[idx] = x[(((size_t)b*3 + c)*224 + (pr*16 + i))*224 + pc*16 + j];
}

// ---------------- assemble tokens: cls + patches + pos_embed; zero residual ----------
__global__ void assemble_kernel(const float* __restrict__ cls, const float* __restrict__ pos) {
    int idx = blockIdx.x * blockDim.x + threadIdx.x;
    if (idx >= MTOK*DIM) return;
    int m = idx / DIM, d = idx - m*DIM;
    int b = m / SEQ, t = m - b*SEQ;
    float v = (t == 0) ? cls[d] : g_y[((size_t)b*NPATCH + (t-1))*DIM + d];
    g_hid[idx] = v + pos[t*DIM + d];
    g_res[idx] = 0.f;
}

// ---------------- block reduction helper (128 threads) ----------------
__device__ __forceinline__ float block_sum_128(float v) {
    __shared__ float sh[4];
#pragma unroll
    for (int o = 16; o > 0; o >>= 1) v += __shfl_down_sync(0xffffffffu, v, o);
    int w = threadIdx.x >> 5, lane = threadIdx.x & 31;
    if (lane == 0) sh[w] = v;
    __syncthreads();
    float r = sh[0] + sh[1] + sh[2] + sh[3];
    __syncthreads();
    return r;
}

// ---------------- residual add + LayerNorm (per token) ----------------
__global__ void resln_kernel(const float* __restrict__ nw, const float* __restrict__ nb) {
    int t = blockIdx.x;                   // token 0..MTOK-1
    float* res = g_res + (size_t)t*DIM;
    const float* hid = g_hid + (size_t)t*DIM;
    float v[3]; float sum = 0.f;
#pragma unroll
    for (int i = 0; i < 3; i++) {
        int d = threadIdx.x + i*128;
        float r = res[d] + hid[d];
        v[i] = r; res[d] = r; sum += r;
    }
    float mu = block_sum_128(sum) * (1.f/DIM);
    float ss = 0.f;
#pragma unroll
    for (int i = 0; i < 3; i++) { float dl = v[i]-mu; ss += dl*dl; }
    float var = block_sum_128(ss) * (1.f/DIM);
    float rstd = rsqrtf(var + 1e-5f);
    float* u = g_u + (size_t)t*DIM;
#pragma unroll
    for (int i = 0; i < 3; i++) {
        int d = threadIdx.x + i*128;
        u[d] = (v[i]-mu)*rstd*nw[d] + nb[d];
    }
}

// ---------------- final LN on cls token only ----------------
__global__ void finalln_kernel(const float* __restrict__ nw, const float* __restrict__ nb) {
    int b = blockIdx.x;                   // 0..15
    size_t off = (size_t)(b*SEQ)*DIM;     // token 0 of batch b
    float v[3]; float sum = 0.f;
#pragma unroll
    for (int i = 0; i < 3; i++) {
        int d = threadIdx.x + i*128;
        float r = g_res[off + d] + g_hid[off + d];
        v[i] = r; sum += r;
    }
    float mu = block_sum_128(sum) * (1.f/DIM);
    float ss = 0.f;
#pragma unroll
    for (int i = 0; i < 3; i++) { float dl = v[i]-mu; ss += dl*dl; }
    float var = block_sum_128(ss) * (1.f/DIM);
    float rstd = rsqrtf(var + 1e-5f);
#pragma unroll
    for (int i = 0; i < 3; i++) {
        int d = threadIdx.x + i*128;
        g_cls[(size_t)b*DIM + d] = (v[i]-mu)*rstd*nw[d] + nb[d];
    }
}

// ---------------- depthwise causal conv1d (k=4, left pad 3) + bias + SiLU --------
__global__ void conv_silu_kernel(const float* __restrict__ wc, const float* __restrict__ bc) {
    int idx = blockIdx.x * blockDim.x + threadIdx.x;
    if (idx >= MTOK*DIN) return;
    int m = idx / DIN, c = idx - m*DIN;
    int b = m / SEQ, l = m - b*SEQ;
    const float* w = wc + c*4;
    float acc = bc[c];
#pragma unroll
    for (int k = 0; k < 4; k++) {
        int ll = l - 3 + k;
        if (ll >= 0) acc += g_xz[((size_t)(b*SEQ + ll))*(2*DIN) + c] * w[k];
    }
    float sg = 1.f / (1.f + __expf(-acc));
    g_xcs[idx] = acc * sg;
}

// ---------------- selective scan + skip + gating -----------------------
// block: (d-chunk, batch); each thread owns one channel, 16 states in regs.
__global__ void scan_kernel(const float* __restrict__ Alog, const float* __restrict__ Dssm) {
    int b = blockIdx.y;
    int d = blockIdx.x*128 + threadIdx.x;
    float Av[DST], s[DST];
#pragma unroll
    for (int n = 0; n < DST; n++) { Av[n] = -__expf(Alog[d*DST + n]); s[n] = 0.f; }
    float Dp = Dssm[d];
    __shared__ float sBC[32];
    for (int l = 0; l < SEQ; l++) {
        int m = b*SEQ + l;
        __syncthreads();
        if (threadIdx.x < 32) sBC[threadIdx.x] = g_dbl[(size_t)m*56 + DTRANK + threadIdx.x];
        __syncthreads();
        float dt = g_dt[(size_t)m*DIN + d];
        float xv = g_xcs[(size_t)m*DIN + d];
        float zv = g_xz[(size_t)m*(2*DIN) + DIN + d];
        float dtx = dt * xv;
        float y = 0.f;
#pragma unroll
        for (int n = 0; n < DST; n++) {
            s[n] = s[n]*__expf(dt*Av[n]) + dtx*sBC[n];
            y += s[n]*sBC[16+n];
        }
        float sg = 1.f / (1.f + __expf(-zv));
        g_y[(size_t)m*DIN + d] = (y + xv*Dp) * (zv*sg);
    }
}

// ---------------- host launcher ----------------
static inline dim3 gemm_grid(int M, int N) { return dim3((N+127)/128, (M+127)/128); }

extern "C" void kernel_launch(void* const* d_in, const int* in_sizes, int n_in,
                              void* d_out, int out_size)
{
    const float* x          = (const float*)d_in[0];
    const float* patch_w    = (const float*)d_in[1];
    const float* patch_b    = (const float*)d_in[2];
    const float* cls_tok    = (const float*)d_in[3];
    const float* pos_emb    = (const float*)d_in[4];
    const float* in_proj_w  = (const float*)d_in[5];
    const float* conv_w     = (const float*)d_in[6];
    const float* conv_b     = (const float*)d_in[7];
    const float* x_proj_w   = (const float*)d_in[8];
    const float* dt_proj_w  = (const float*)d_in[9];
    const float* dt_proj_b  = (const float*)d_in[10];
    const float* A_log      = (const float*)d_in[11];
    const float* D_ssm      = (const float*)d_in[12];
    const float* out_proj_w = (const float*)d_in[13];
    const float* norm_w     = (const float*)d_in[14];
    const float* norm_b     = (const float*)d_in[15];
    const float* normf_w    = (const float*)d_in[16];
    const float* normf_b    = (const float*)d_in[17];
    const float* head_w     = (const float*)d_in[18];
    const float* head_b     = (const float*)d_in[19];
    float* out = (float*)d_out;

    float *p_im2col, *p_u, *p_xz, *p_xcs, *p_dbl, *p_dt, *p_y, *p_hid, *p_cls;
    cudaGetSymbolAddress((void**)&p_im2col, g_im2col);
    cudaGetSymbolAddress((void**)&p_u,      g_u);
    cudaGetSymbolAddress((void**)&p_xz,     g_xz);
    cudaGetSymbolAddress((void**)&p_xcs,    g_xcs);
    cudaGetSymbolAddress((void**)&p_dbl,    g_dbl);
    cudaGetSymbolAddress((void**)&p_dt,     g_dt);
    cudaGetSymbolAddress((void**)&p_y,      g_y);
    cudaGetSymbolAddress((void**)&p_hid,    g_hid);
    cudaGetSymbolAddress((void**)&p_cls,    g_cls);

    // patch embed: im2col -> GEMM (+bias) into g_y (token scratch)
    im2col_kernel<<<(MPATCH*KPATCH + 255)/256, 256>>>(x);
    gemm_nt<<<gemm_grid(MPATCH, DIM), 256>>>(p_im2col, KPATCH, patch_w, KPATCH,
                                             p_y, DIM, patch_b, MPATCH, DIM, KPATCH, 1);
    assemble_kernel<<<(MTOK*DIM + 255)/256, 256>>>(cls_tok, pos_emb);

    for (int L = 0; L < NLAYER; L++) {
        resln_kernel<<<MTOK, 128>>>(norm_w + L*DIM, norm_b + L*DIM);
        // in_proj: (3152 x 384) @ (1536 x 384)^T -> xz
        gemm_nt<<<gemm_grid(MTOK, 2*DIN), 256>>>(p_u, DIM,
            in_proj_w + (size_t)L*2*DIN*DIM, DIM, p_xz, 2*DIN, (const float*)0,
            MTOK, 2*DIN, DIM, 0);
        conv_silu_kernel<<<(MTOK*DIN + 255)/256, 256>>>(conv_w + L*DIN*4, conv_b + L*DIN);
        // x_proj: (3152 x 768) @ (56 x 768)^T -> dbl
        gemm_nt<<<gemm_grid(MTOK, 56), 256>>>(p_xcs, DIN,
            x_proj_w + (size_t)L*56*DIN, DIN, p_dbl, 56, (const float*)0,
            MTOK, 56, DIN, 0);
        // dt_proj: (3152 x 24 [lda=56]) @ (768 x 24)^T + bias -> softplus -> dt
        gemm_nt<<<gemm_grid(MTOK, DIN), 256>>>(p_dbl, 56,
            dt_proj_w + (size_t)L*DIN*DTRANK, DTRANK, p_dt, DIN,
            dt_proj_b + L*DIN, MTOK, DIN, DTRANK, 2);
        scan_kernel<<<dim3(DIN/128, BATCH), 128>>>(A_log + (size_t)L*DIN*DST, D_ssm + L*DIN);
        // out_proj: (3152 x 768) @ (384 x 768)^T -> hid
        gemm_nt<<<gemm_grid(MTOK, DIM), 256>>>(p_y, DIN,
            out_proj_w + (size_t)L*DIM*DIN, DIN, p_hid, DIM, (const float*)0,
            MTOK, DIM, DIN, 0);
    }

    finalln_kernel<<<BATCH, 128>>>(normf_w, normf_b);
    // head: (16 x 384) @ (1000 x 384)^T + bias -> out
    gemm_nt<<<gemm_grid(BATCH, NCLS), 256>>>(p_cls, DIM, head_w, DIM,
                                             out, NCLS, head_b, BATCH, NCLS, DIM, 1);
}

// round 6
// speedup vs baseline: 1.3758x; 1.3758x over previous
#include <cuda_runtime.h>
#include <math.h>

// ---------------- problem constants ----------------
#define BATCH   16
#define SEQ     197
#define DIM     384
#define NLAYER  24
#define DIN     768
#define DST     16
#define DTRANK  24
#define NCLS    1000
#define MTOK    (BATCH*SEQ)       // 3152
#define NPATCH  196
#define MPATCH  (BATCH*NPATCH)    // 3136
#define KPATCH  768               // 3*16*16
#define KC      8                 // GEMM k-chunk

// ---------------- device scratch (no cudaMalloc allowed) ----------------
__device__ float g_im2col[MPATCH*KPATCH];
__device__ float g_hid[MTOK*DIM];
__device__ float g_res[MTOK*DIM];
__device__ float g_u[MTOK*DIM];
__device__ float g_xz[MTOK*2*DIN];
__device__ float g_xcs[MTOK*DIN];
__device__ float g_dbl[MTOK*56];
__device__ float g_dt[MTOK*DIN];
__device__ float g_y[MTOK*DIN];
__device__ float g_cls[BATCH*DIM];

// ============================================================================
// gemm_big: C[m,n] = sum_k A[m,k]*B[n,k]  (NT), 128x64 tile, 256 thr, 8x4 micro
// Double-buffered smem, one __syncthreads per k-chunk, register prefetch.
// Requires K%8==0, lda/ldb%4==0, A/B/C 16B-aligned. epi:0 none,1 +bias,2 softplus(+bias)
// ============================================================================
__global__ void __launch_bounds__(256, 3) gemm_big(
    const float* __restrict__ A, int lda,
    const float* __restrict__ B, int ldb,
    float* __restrict__ C, int ldc,
    const float* __restrict__ bias,
    int M, int N, int K, int epi)
{
    __shared__ __align__(16) float As[2][KC][132];
    __shared__ __align__(16) float Bs[2][KC][68];

    const int tid = threadIdx.x;
    const int tx  = tid & 15;          // 16 col groups (4 cols each)
    const int ty  = tid >> 4;          // 16 row groups (8 rows each)
    const int row0 = blockIdx.y * 128;
    const int col0 = blockIdx.x * 64;

    // load mapping
    const int lrA = tid >> 1;          // 0..127
    const int lcA = (tid & 1) << 2;    // 0 or 4
    const bool doB = (tid < 128);
    const int lrB = (tid & 127) >> 1;  // 0..63
    const int lcB = lcA;

    const int ar = row0 + lrA;
    const int br = col0 + lrB;
    const bool aval = (ar < M);
    const bool bval = doB && (br < N);
    const float* Ap = A + (size_t)ar * lda + lcA;
    const float* Bp = B + (size_t)br * ldb + lcB;

    float acc[8][4];
#pragma unroll
    for (int i = 0; i < 8; i++)
#pragma unroll
        for (int j = 0; j < 4; j++) acc[i][j] = 0.f;

    const int NC = K / KC;
    float4 pa = make_float4(0.f,0.f,0.f,0.f);
    float4 pb = make_float4(0.f,0.f,0.f,0.f);
    if (aval) pa = *(const float4*)Ap;
    if (bval) pb = *(const float4*)Bp;

    int s = 0;
    As[0][lcA+0][lrA]=pa.x; As[0][lcA+1][lrA]=pa.y; As[0][lcA+2][lrA]=pa.z; As[0][lcA+3][lrA]=pa.w;
    if (doB) { Bs[0][lcB+0][lrB]=pb.x; Bs[0][lcB+1][lrB]=pb.y; Bs[0][lcB+2][lrB]=pb.z; Bs[0][lcB+3][lrB]=pb.w; }
    __syncthreads();

    for (int c = 1; c <= NC; ++c) {
        const bool more = (c < NC);
        if (more) {
            pa = aval ? *(const float4*)(Ap + c*KC) : make_float4(0.f,0.f,0.f,0.f);
            if (doB) pb = bval ? *(const float4*)(Bp + c*KC) : make_float4(0.f,0.f,0.f,0.f);
        }
#pragma unroll
        for (int k = 0; k < KC; ++k) {
            float4 a0 = *(const float4*)&As[s][k][ty*8];
            float4 a1 = *(const float4*)&As[s][k][ty*8+4];
            float4 b0 = *(const float4*)&Bs[s][k][tx*4];
            float ra[8] = {a0.x,a0.y,a0.z,a0.w,a1.x,a1.y,a1.z,a1.w};
            float rb[4] = {b0.x,b0.y,b0.z,b0.w};
#pragma unroll
            for (int i = 0; i < 8; i++)
#pragma unroll
                for (int j = 0; j < 4; j++)
                    acc[i][j] += ra[i]*rb[j];
        }
        if (more) {
            int t = s ^ 1;
            As[t][lcA+0][lrA]=pa.x; As[t][lcA+1][lrA]=pa.y; As[t][lcA+2][lrA]=pa.z; As[t][lcA+3][lrA]=pa.w;
            if (doB) { Bs[t][lcB+0][lrB]=pb.x; Bs[t][lcB+1][lrB]=pb.y; Bs[t][lcB+2][lrB]=pb.z; Bs[t][lcB+3][lrB]=pb.w; }
            __syncthreads();
            s = t;
        }
    }

#pragma unroll
    for (int i = 0; i < 8; i++) {
        int r = row0 + ty*8 + i;
        if (r < M) {
#pragma unroll
            for (int j = 0; j < 4; j++) {
                int cc = col0 + tx*4 + j;
                if (cc < N) {
                    float v = acc[i][j];
                    if (epi) {
                        v += bias[cc];
                        if (epi == 2) v = (v > 20.f) ? v : log1pf(expf(v));
                    }
                    C[(size_t)r*ldc + cc] = v;
                }
            }
        }
    }
}

// ============================================================================
// gemm_small: 32x64 tile, 64 thr, 4x8 micro. For x_proj (N=56) -> 99 CTAs.
// ============================================================================
__global__ void __launch_bounds__(64) gemm_small(
    const float* __restrict__ A, int lda,
    const float* __restrict__ B, int ldb,
    float* __restrict__ C, int ldc,
    int M, int N, int K)
{
    __shared__ __align__(16) float As[2][KC][36];
    __shared__ __align__(16) float Bs[2][KC][68];

    const int tid = threadIdx.x;
    const int tx  = tid & 7;           // 8 col groups (8 cols each)
    const int ty  = tid >> 3;          // 8 row groups (4 rows each)
    const int row0 = blockIdx.y * 32;
    const int col0 = blockIdx.x * 64;

    const int lrA = tid >> 1;          // 0..31
    const int lcA = (tid & 1) << 2;
    const int lrB = tid;               // 0..63

    const int ar = row0 + lrA;
    const int br = col0 + lrB;
    const bool aval = (ar < M);
    const bool bval = (br < N);
    const float* Ap = A + (size_t)ar * lda + lcA;
    const float* Bp = B + (size_t)br * ldb;

    float acc[4][8];
#pragma unroll
    for (int i = 0; i < 4; i++)
#pragma unroll
        for (int j = 0; j < 8; j++) acc[i][j] = 0.f;

    const int NC = K / KC;
    float4 pa = make_float4(0.f,0.f,0.f,0.f);
    float4 pb0 = pa, pb1 = pa;
    if (aval) pa = *(const float4*)Ap;
    if (bval) { pb0 = *(const float4*)Bp; pb1 = *(const float4*)(Bp+4); }

    int s = 0;
    As[0][lcA+0][lrA]=pa.x; As[0][lcA+1][lrA]=pa.y; As[0][lcA+2][lrA]=pa.z; As[0][lcA+3][lrA]=pa.w;
    Bs[0][0][lrB]=pb0.x; Bs[0][1][lrB]=pb0.y; Bs[0][2][lrB]=pb0.z; Bs[0][3][lrB]=pb0.w;
    Bs[0][4][lrB]=pb1.x; Bs[0][5][lrB]=pb1.y; Bs[0][6][lrB]=pb1.z; Bs[0][7][lrB]=pb1.w;
    __syncthreads();

    for (int c = 1; c <= NC; ++c) {
        const bool more = (c < NC);
        if (more) {
            pa  = aval ? *(const float4*)(Ap + c*KC) : make_float4(0.f,0.f,0.f,0.f);
            pb0 = bval ? *(const float4*)(Bp + c*KC) : make_float4(0.f,0.f,0.f,0.f);
            pb1 = bval ? *(const float4*)(Bp + c*KC + 4) : make_float4(0.f,0.f,0.f,0.f);
        }
#pragma unroll
        for (int k = 0; k < KC; ++k) {
            float4 a0 = *(const float4*)&As[s][k][ty*4];
            float4 b0 = *(const float4*)&Bs[s][k][tx*8];
            float4 b1 = *(const float4*)&Bs[s][k][tx*8+4];
            float ra[4] = {a0.x,a0.y,a0.z,a0.w};
            float rb[8] = {b0.x,b0.y,b0.z,b0.w,b1.x,b1.y,b1.z,b1.w};
#pragma unroll
            for (int i = 0; i < 4; i++)
#pragma unroll
                for (int j = 0; j < 8; j++)
                    acc[i][j] += ra[i]*rb[j];
        }
        if (more) {
            int t = s ^ 1;
            As[t][lcA+0][lrA]=pa.x; As[t][lcA+1][lrA]=pa.y; As[t][lcA+2][lrA]=pa.z; As[t][lcA+3][lrA]=pa.w;
            Bs[t][0][lrB]=pb0.x; Bs[t][1][lrB]=pb0.y; Bs[t][2][lrB]=pb0.z; Bs[t][3][lrB]=pb0.w;
            Bs[t][4][lrB]=pb1.x; Bs[t][5][lrB]=pb1.y; Bs[t][6][lrB]=pb1.z; Bs[t][7][lrB]=pb1.w;
            __syncthreads();
            s = t;
        }
    }

#pragma unroll
    for (int i = 0; i < 4; i++) {
        int r = row0 + ty*4 + i;
        if (r < M) {
#pragma unroll
            for (int j = 0; j < 8; j++) {
                int cc = col0 + tx*8 + j;
                if (cc < N) C[(size_t)r*ldc + cc] = acc[i][j];
            }
        }
    }
}

// ---------------- im2col for 16x16/stride16 patch conv ----------------
__global__ void im2col_kernel(const float* __restrict__ x) {
    int idx = blockIdx.x * blockDim.x + threadIdx.x;
    if (idx >= MPATCH*KPATCH) return;
    int m = idx / KPATCH, k = idx - m*KPATCH;
    int b = m / NPATCH,  p = m - b*NPATCH;
    int pr = p / 14, pc = p - pr*14;
    int c = k >> 8, r = k & 255;
    int i = r >> 4, j = r & 15;
    g_im2col[idx] = x[(((size_t)b*3 + c)*224 + (pr*16 + i))*224 + pc*16 + j];
}

// ---------------- assemble tokens + pos_embed; zero residual ----------
__global__ void assemble_kernel(const float* __restrict__ cls, const float* __restrict__ pos) {
    int idx = blockIdx.x * blockDim.x + threadIdx.x;
    if (idx >= MTOK*DIM) return;
    int m = idx / DIM, d = idx - m*DIM;
    int b = m / SEQ, t = m - b*SEQ;
    float v = (t == 0) ? cls[d] : g_y[((size_t)b*NPATCH + (t-1))*DIM + d];
    g_hid[idx] = v + pos[t*DIM + d];
    g_res[idx] = 0.f;
}

// ---------------- block reduction (96 threads = 3 warps) ----------------
__device__ __forceinline__ float block_sum_96(float v) {
    __shared__ float sh[3];
#pragma unroll
    for (int o = 16; o > 0; o >>= 1) v += __shfl_down_sync(0xffffffffu, v, o);
    int w = threadIdx.x >> 5, lane = threadIdx.x & 31;
    if (lane == 0) sh[w] = v;
    __syncthreads();
    float r = sh[0] + sh[1] + sh[2];
    __syncthreads();
    return r;
}

// ---------------- residual add + LayerNorm (per token, float4) ----------------
__global__ void resln_kernel(const float* __restrict__ nw, const float* __restrict__ nb) {
    int t = blockIdx.x;
    int i = threadIdx.x;                 // 0..95
    float4* res4 = (float4*)(g_res + (size_t)t*DIM);
    const float4* hid4 = (const float4*)(g_hid + (size_t)t*DIM);
    float4 v = res4[i];
    float4 h = hid4[i];
    v.x += h.x; v.y += h.y; v.z += h.z; v.w += h.w;
    res4[i] = v;
    float mu = block_sum_96(v.x+v.y+v.z+v.w) * (1.f/DIM);
    float dx=v.x-mu, dy=v.y-mu, dz=v.z-mu, dw=v.w-mu;
    float var = block_sum_96(dx*dx+dy*dy+dz*dz+dw*dw) * (1.f/DIM);
    float rstd = rsqrtf(var + 1e-5f);
    float4 w4 = ((const float4*)nw)[i];
    float4 b4 = ((const float4*)nb)[i];
    float4 o;
    o.x = dx*rstd*w4.x + b4.x;
    o.y = dy*rstd*w4.y + b4.y;
    o.z = dz*rstd*w4.z + b4.z;
    o.w = dw*rstd*w4.w + b4.w;
    ((float4*)(g_u + (size_t)t*DIM))[i] = o;
}

// ---------------- final LN on cls token only ----------------
__global__ void finalln_kernel(const float* __restrict__ nw, const float* __restrict__ nb) {
    int b = blockIdx.x;
    int i = threadIdx.x;                 // 0..95
    size_t off = (size_t)(b*SEQ)*DIM;
    float4 v = ((const float4*)(g_res + off))[i];
    float4 h = ((const float4*)(g_hid + off))[i];
    v.x += h.x; v.y += h.y; v.z += h.z; v.w += h.w;
    float mu = block_sum_96(v.x+v.y+v.z+v.w) * (1.f/DIM);
    float dx=v.x-mu, dy=v.y-mu, dz=v.z-mu, dw=v.w-mu;
    float var = block_sum_96(dx*dx+dy*dy+dz*dz+dw*dw) * (1.f/DIM);
    float rstd = rsqrtf(var + 1e-5f);
    float4 w4 = ((const float4*)nw)[i];
    float4 b4 = ((const float4*)nb)[i];
    float4 o;
    o.x = dx*rstd*w4.x + b4.x;
    o.y = dy*rstd*w4.y + b4.y;
    o.z = dz*rstd*w4.z + b4.z;
    o.w = dw*rstd*w4.w + b4.w;
    ((float4*)(g_cls + (size_t)b*DIM))[i] = o;
}

// ---------------- depthwise causal conv1d (k=4) + bias + SiLU --------
__global__ void conv_silu_kernel(const float* __restrict__ wc, const float* __restrict__ bc) {
    int idx = blockIdx.x * blockDim.x + threadIdx.x;
    if (idx >= MTOK*DIN) return;
    int m = idx / DIN, c = idx - m*DIN;
    int b = m / SEQ, l = m - b*SEQ;
    const float* w = wc + c*4;
    float acc = bc[c];
#pragma unroll
    for (int k = 0; k < 4; k++) {
        int ll = l - 3 + k;
        if (ll >= 0) acc += g_xz[((size_t)(b*SEQ + ll))*(2*DIN) + c] * w[k];
    }
    float sg = 1.f / (1.f + __expf(-acc));
    g_xcs[idx] = acc * sg;
}

// ---------------- selective scan + skip + gating (double-buffered BC) --------
__global__ void scan_kernel(const float* __restrict__ Alog, const float* __restrict__ Dssm) {
    int b = blockIdx.y;
    int d = blockIdx.x*128 + threadIdx.x;
    float Av[DST], s[DST];
#pragma unroll
    for (int n = 0; n < DST; n++) { Av[n] = -__expf(Alog[d*DST + n]); s[n] = 0.f; }
    float Dp = Dssm[d];
    __shared__ float sBC[2][32];
    if (threadIdx.x < 32)
        sBC[0][threadIdx.x] = g_dbl[(size_t)(b*SEQ)*56 + DTRANK + threadIdx.x];
    __syncthreads();
    for (int l = 0; l < SEQ; l++) {
        int m = b*SEQ + l;
        int cur = l & 1;
        if (l + 1 < SEQ && threadIdx.x < 32)
            sBC[cur^1][threadIdx.x] = g_dbl[(size_t)(m+1)*56 + DTRANK + threadIdx.x];
        float dt = g_dt[(size_t)m*DIN + d];
        float xv = g_xcs[(size_t)m*DIN + d];
        float zv = g_xz[(size_t)m*(2*DIN) + DIN + d];
        float dtx = dt * xv;
        float y = 0.f;
#pragma unroll
        for (int n = 0; n < DST; n++) {
            s[n] = s[n]*__expf(dt*Av[n]) + dtx*sBC[cur][n];
            y += s[n]*sBC[cur][16+n];
        }
        float sg = 1.f / (1.f + __expf(-zv));
        g_y[(size_t)m*DIN + d] = (y + xv*Dp) * (zv*sg);
        __syncthreads();
    }
}

// ---------------- host launcher ----------------
static inline dim3 big_grid(int M, int N) { return dim3((N+63)/64, (M+127)/128); }

extern "C" void kernel_launch(void* const* d_in, const int* in_sizes, int n_in,
                              void* d_out, int out_size)
{
    const float* x          = (const float*)d_in[0];
    const float* patch_w    = (const float*)d_in[1];
    const float* patch_b    = (const float*)d_in[2];
    const float* cls_tok    = (const float*)d_in[3];
    const float* pos_emb    = (const float*)d_in[4];
    const float* in_proj_w  = (const float*)d_in[5];
    const float* conv_w     = (const float*)d_in[6];
    const float* conv_b     = (const float*)d_in[7];
    const float* x_proj_w   = (const float*)d_in[8];
    const float* dt_proj_w  = (const float*)d_in[9];
    const float* dt_proj_b  = (const float*)d_in[10];
    const float* A_log      = (const float*)d_in[11];
    const float* D_ssm      = (const float*)d_in[12];
    const float* out_proj_w = (const float*)d_in[13];
    const float* norm_w     = (const float*)d_in[14];
    const float* norm_b     = (const float*)d_in[15];
    const float* normf_w    = (const float*)d_in[16];
    const float* normf_b    = (const float*)d_in[17];
    const float* head_w     = (const float*)d_in[18];
    const float* head_b     = (const float*)d_in[19];
    float* out = (float*)d_out;

    float *p_im2col, *p_u, *p_xz, *p_xcs, *p_dbl, *p_dt, *p_y, *p_hid, *p_cls;
    cudaGetSymbolAddress((void**)&p_im2col, g_im2col);
    cudaGetSymbolAddress((void**)&p_u,      g_u);
    cudaGetSymbolAddress((void**)&p_xz,     g_xz);
    cudaGetSymbolAddress((void**)&p_xcs,    g_xcs);
    cudaGetSymbolAddress((void**)&p_dbl,    g_dbl);
    cudaGetSymbolAddress((void**)&p_dt,     g_dt);
    cudaGetSymbolAddress((void**)&p_y,      g_y);
    cudaGetSymbolAddress((void**)&p_hid,    g_hid);
    cudaGetSymbolAddress((void**)&p_cls,    g_cls);

    // patch embed: im2col -> GEMM (+bias) into g_y
    im2col_kernel<<<(MPATCH*KPATCH + 255)/256, 256>>>(x);
    gemm_big<<<big_grid(MPATCH, DIM), 256>>>(p_im2col, KPATCH, patch_w, KPATCH,
                                             p_y, DIM, patch_b, MPATCH, DIM, KPATCH, 1);
    assemble_kernel<<<(MTOK*DIM + 255)/256, 256>>>(cls_tok, pos_emb);

    for (int L = 0; L < NLAYER; L++) {
        resln_kernel<<<MTOK, 96>>>(norm_w + L*DIM, norm_b + L*DIM);
        // in_proj: (3152 x 384) @ (1536 x 384)^T -> xz   [600 CTAs]
        gemm_big<<<big_grid(MTOK, 2*DIN), 256>>>(p_u, DIM,
            in_proj_w + (size_t)L*2*DIN*DIM, DIM, p_xz, 2*DIN, (const float*)0,
            MTOK, 2*DIN, DIM, 0);
        conv_silu_kernel<<<(MTOK*DIN + 255)/256, 256>>>(conv_w + L*DIN*4, conv_b + L*DIN);
        // x_proj: (3152 x 768) @ (56 x 768)^T -> dbl   [99 CTAs, small kernel]
        gemm_small<<<dim3(1, (MTOK+31)/32), 64>>>(p_xcs, DIN,
            x_proj_w + (size_t)L*56*DIN, DIN, p_dbl, 56, MTOK, 56, DIN);
        // dt_proj: (3152 x 24) @ (768 x 24)^T + bias -> softplus
        gemm_big<<<big_grid(MTOK, DIN), 256>>>(p_dbl, 56,
            dt_proj_w + (size_t)L*DIN*DTRANK, DTRANK, p_dt, DIN,
            dt_proj_b + L*DIN, MTOK, DIN, DTRANK, 2);
        scan_kernel<<<dim3(DIN/128, BATCH), 128>>>(A_log + (size_t)L*DIN*DST, D_ssm + L*DIN);
        // out_proj: (3152 x 768) @ (384 x 768)^T -> hid   [150 CTAs]
        gemm_big<<<big_grid(MTOK, DIM), 256>>>(p_y, DIN,
            out_proj_w + (size_t)L*DIM*DIN, DIN, p_hid, DIM, (const float*)0,
            MTOK, DIM, DIN, 0);
    }

    finalln_kernel<<<BATCH, 96>>>(normf_w, normf_b);
    gemm_big<<<big_grid(BATCH, NCLS), 256>>>(p_cls, DIM, head_w, DIM,
                                             out, NCLS, head_b, BATCH, NCLS, DIM, 1);
}

// round 7
// speedup vs baseline: 1.7652x; 1.2830x over previous
#include <cuda_runtime.h>
#include <math.h>
#include <stdint.h>

// ---------------- problem constants ----------------
#define BATCH   16
#define SEQ     197
#define DIM     384
#define NLAYER  24
#define DIN     768
#define DST     16
#define DTRANK  24
#define NCLS    1000
#define MTOK    (BATCH*SEQ)       // 3152
#define NPATCH  196
#define MPATCH  (BATCH*NPATCH)    // 3136
#define KPATCH  768
#define KC      8                 // fp32 GEMM k-chunk

// ---------------- device scratch ----------------
__device__ float g_im2col[MPATCH*KPATCH];
__device__ float g_hid[MTOK*DIM];
__device__ float g_res[MTOK*DIM];
__device__ float g_u[MTOK*DIM];
__device__ float g_xz[MTOK*2*DIN];
__device__ float g_xcs[MTOK*DIN];
__device__ float g_dbl[MTOK*56];
__device__ float g_dt[MTOK*DIN];
__device__ float g_y[MTOK*DIN];
__device__ float g_cls[BATCH*DIM];

// ============================================================================
// TF32 tensor-core GEMM (NT): C[m,n] = sum_k A[m,k]*B[n,k]
// 128x128x16 tile, 256 thr (8 warps 2x4), warp 64x32 (4x4 m16n8k8 mmas).
// Smem [row][k] stride 20 words -> conflict-free fragment loads.
// Requires: K%16==0, N%128==0, lda/ldb%4==0. epi: 0 none, 1 +bias[n].
// ============================================================================
__device__ __forceinline__ uint32_t f2tf(float f) {
    uint32_t u;
    asm("cvt.rna.tf32.f32 %0, %1;" : "=r"(u) : "f"(f));
    return u;
}

__global__ void __launch_bounds__(256, 2) gemm_tf32(
    const float* __restrict__ A, int lda,
    const float* __restrict__ B, int ldb,
    float* __restrict__ C, int ldc,
    const float* __restrict__ bias,
    int M, int N, int K, int epi)
{
    __shared__ uint32_t As[2][128][20];
    __shared__ uint32_t Bs[2][128][20];

    const int tid  = threadIdx.x;
    const int lane = tid & 31;
    const int wid  = tid >> 5;
    const int g    = lane >> 2;       // group id 0..7
    const int t    = lane & 3;        // thread-in-group 0..3
    const int wm   = wid & 1;         // 2 warps in M
    const int wn   = wid >> 1;        // 4 warps in N
    const int m_base = wm * 64;
    const int n_base = wn * 32;

    const int row0 = blockIdx.y * 128;
    const int col0 = blockIdx.x * 128;

    // g2s mapping: thread loads 2 float4 per operand per chunk
    const int lrow = tid >> 2;        // 0..63
    const int lc4  = (tid & 3) << 2;  // 0,4,8,12

    const int ar0 = row0 + lrow,      ar1 = row0 + lrow + 64;
    const int br0 = col0 + lrow,      br1 = col0 + lrow + 64;
    const bool av0 = ar0 < M, av1 = ar1 < M;
    const bool bv0 = br0 < N, bv1 = br1 < N;
    const float* Ap0 = A + (size_t)ar0 * lda + lc4;
    const float* Ap1 = A + (size_t)ar1 * lda + lc4;
    const float* Bp0 = B + (size_t)br0 * ldb + lc4;
    const float* Bp1 = B + (size_t)br1 * ldb + lc4;

    float d[4][4][4];
#pragma unroll
    for (int mi = 0; mi < 4; mi++)
#pragma unroll
        for (int ni = 0; ni < 4; ni++)
#pragma unroll
            for (int r = 0; r < 4; r++) d[mi][ni][r] = 0.f;

    const int NCH = K / 16;
    const float4 z4 = make_float4(0.f,0.f,0.f,0.f);
    float4 pa0 = av0 ? *(const float4*)Ap0 : z4;
    float4 pa1 = av1 ? *(const float4*)Ap1 : z4;
    float4 pb0 = bv0 ? *(const float4*)Bp0 : z4;
    float4 pb1 = bv1 ? *(const float4*)Bp1 : z4;

    int s = 0;
    {
        uint32_t* a0 = &As[0][lrow][lc4];
        uint32_t* a1 = &As[0][lrow+64][lc4];
        uint32_t* b0 = &Bs[0][lrow][lc4];
        uint32_t* b1 = &Bs[0][lrow+64][lc4];
        a0[0]=f2tf(pa0.x); a0[1]=f2tf(pa0.y); a0[2]=f2tf(pa0.z); a0[3]=f2tf(pa0.w);
        a1[0]=f2tf(pa1.x); a1[1]=f2tf(pa1.y); a1[2]=f2tf(pa1.z); a1[3]=f2tf(pa1.w);
        b0[0]=f2tf(pb0.x); b0[1]=f2tf(pb0.y); b0[2]=f2tf(pb0.z); b0[3]=f2tf(pb0.w);
        b1[0]=f2tf(pb1.x); b1[1]=f2tf(pb1.y); b1[2]=f2tf(pb1.z); b1[3]=f2tf(pb1.w);
    }
    __syncthreads();

    for (int c = 1; c <= NCH; ++c) {
        const bool more = (c < NCH);
        if (more) {
            int kc = c * 16;
            pa0 = av0 ? *(const float4*)(Ap0 + kc) : z4;
            pa1 = av1 ? *(const float4*)(Ap1 + kc) : z4;
            pb0 = bv0 ? *(const float4*)(Bp0 + kc) : z4;
            pb1 = bv1 ? *(const float4*)(Bp1 + kc) : z4;
        }
#pragma unroll
        for (int kk = 0; kk < 2; kk++) {
            const int k0 = kk * 8;
            uint32_t af[4][4], bf[4][2];
#pragma unroll
            for (int mi = 0; mi < 4; mi++) {
                const int m0 = m_base + mi*16;
                af[mi][0] = As[s][m0 + g    ][k0 + t    ];
                af[mi][1] = As[s][m0 + g + 8][k0 + t    ];
                af[mi][2] = As[s][m0 + g    ][k0 + t + 4];
                af[mi][3] = As[s][m0 + g + 8][k0 + t + 4];
            }
#pragma unroll
            for (int ni = 0; ni < 4; ni++) {
                const int n0 = n_base + ni*8;
                bf[ni][0] = Bs[s][n0 + g][k0 + t    ];
                bf[ni][1] = Bs[s][n0 + g][k0 + t + 4];
            }
#pragma unroll
            for (int mi = 0; mi < 4; mi++)
#pragma unroll
                for (int ni = 0; ni < 4; ni++) {
                    asm volatile(
                        "mma.sync.aligned.m16n8k8.row.col.f32.tf32.tf32.f32 "
                        "{%0,%1,%2,%3}, {%4,%5,%6,%7}, {%8,%9}, {%0,%1,%2,%3};"
                        : "+f"(d[mi][ni][0]), "+f"(d[mi][ni][1]),
                          "+f"(d[mi][ni][2]), "+f"(d[mi][ni][3])
                        : "r"(af[mi][0]), "r"(af[mi][1]), "r"(af[mi][2]), "r"(af[mi][3]),
                          "r"(bf[ni][0]), "r"(bf[ni][1]));
                }
        }
        if (more) {
            int tbuf = s ^ 1;
            uint32_t* a0 = &As[tbuf][lrow][lc4];
            uint32_t* a1 = &As[tbuf][lrow+64][lc4];
            uint32_t* b0 = &Bs[tbuf][lrow][lc4];
            uint32_t* b1 = &Bs[tbuf][lrow+64][lc4];
            a0[0]=f2tf(pa0.x); a0[1]=f2tf(pa0.y); a0[2]=f2tf(pa0.z); a0[3]=f2tf(pa0.w);
            a1[0]=f2tf(pa1.x); a1[1]=f2tf(pa1.y); a1[2]=f2tf(pa1.z); a1[3]=f2tf(pa1.w);
            b0[0]=f2tf(pb0.x); b0[1]=f2tf(pb0.y); b0[2]=f2tf(pb0.z); b0[3]=f2tf(pb0.w);
            b1[0]=f2tf(pb1.x); b1[1]=f2tf(pb1.y); b1[2]=f2tf(pb1.z); b1[3]=f2tf(pb1.w);
            __syncthreads();
            s = tbuf;
        }
    }

    // epilogue
#pragma unroll
    for (int mi = 0; mi < 4; mi++) {
        const int r0 = row0 + m_base + mi*16 + g;
        const int r1 = r0 + 8;
#pragma unroll
        for (int ni = 0; ni < 4; ni++) {
            const int cc = col0 + n_base + ni*8 + 2*t;
            float b0f = 0.f, b1f = 0.f;
            if (epi) { b0f = bias[cc]; b1f = bias[cc+1]; }
            if (r0 < M) {
                C[(size_t)r0*ldc + cc    ] = d[mi][ni][0] + b0f;
                C[(size_t)r0*ldc + cc + 1] = d[mi][ni][1] + b1f;
            }
            if (r1 < M) {
                C[(size_t)r1*ldc + cc    ] = d[mi][ni][2] + b0f;
                C[(size_t)r1*ldc + cc + 1] = d[mi][ni][3] + b1f;
            }
        }
    }
}

// ============================================================================
// fp32 fallback GEMM (dt_proj, head): 128x64 tile, 256 thr, 8x4 micro
// ============================================================================
__global__ void __launch_bounds__(256, 3) gemm_big(
    const float* __restrict__ A, int lda,
    const float* __restrict__ B, int ldb,
    float* __restrict__ C, int ldc,
    const float* __restrict__ bias,
    int M, int N, int K, int epi)
{
    __shared__ __align__(16) float As[2][KC][132];
    __shared__ __align__(16) float Bs[2][KC][68];

    const int tid = threadIdx.x;
    const int tx  = tid & 15;
    const int ty  = tid >> 4;
    const int row0 = blockIdx.y * 128;
    const int col0 = blockIdx.x * 64;

    const int lrA = tid >> 1;
    const int lcA = (tid & 1) << 2;
    const bool doB = (tid < 128);
    const int lrB = (tid & 127) >> 1;
    const int lcB = lcA;

    const int ar = row0 + lrA;
    const int br = col0 + lrB;
    const bool aval = (ar < M);
    const bool bval = doB && (br < N);
    const float* Ap = A + (size_t)ar * lda + lcA;
    const float* Bp = B + (size_t)br * ldb + lcB;

    float acc[8][4];
#pragma unroll
    for (int i = 0; i < 8; i++)
#pragma unroll
        for (int j = 0; j < 4; j++) acc[i][j] = 0.f;

    const int NC = K / KC;
    float4 pa = make_float4(0.f,0.f,0.f,0.f);
    float4 pb = make_float4(0.f,0.f,0.f,0.f);
    if (aval) pa = *(const float4*)Ap;
    if (bval) pb = *(const float4*)Bp;

    int s = 0;
    As[0][lcA+0][lrA]=pa.x; As[0][lcA+1][lrA]=pa.y; As[0][lcA+2][lrA]=pa.z; As[0][lcA+3][lrA]=pa.w;
    if (doB) { Bs[0][lcB+0][lrB]=pb.x; Bs[0][lcB+1][lrB]=pb.y; Bs[0][lcB+2][lrB]=pb.z; Bs[0][lcB+3][lrB]=pb.w; }
    __syncthreads();

    for (int c = 1; c <= NC; ++c) {
        const bool more = (c < NC);
        if (more) {
            pa = aval ? *(const float4*)(Ap + c*KC) : make_float4(0.f,0.f,0.f,0.f);
            if (doB) pb = bval ? *(const float4*)(Bp + c*KC) : make_float4(0.f,0.f,0.f,0.f);
        }
#pragma unroll
        for (int k = 0; k < KC; ++k) {
            float4 a0 = *(const float4*)&As[s][k][ty*8];
            float4 a1 = *(const float4*)&As[s][k][ty*8+4];
            float4 b0 = *(const float4*)&Bs[s][k][tx*4];
            float ra[8] = {a0.x,a0.y,a0.z,a0.w,a1.x,a1.y,a1.z,a1.w};
            float rb[4] = {b0.x,b0.y,b0.z,b0.w};
#pragma unroll
            for (int i = 0; i < 8; i++)
#pragma unroll
                for (int j = 0; j < 4; j++)
                    acc[i][j] += ra[i]*rb[j];
        }
        if (more) {
            int tb = s ^ 1;
            As[tb][lcA+0][lrA]=pa.x; As[tb][lcA+1][lrA]=pa.y; As[tb][lcA+2][lrA]=pa.z; As[tb][lcA+3][lrA]=pa.w;
            if (doB) { Bs[tb][lcB+0][lrB]=pb.x; Bs[tb][lcB+1][lrB]=pb.y; Bs[tb][lcB+2][lrB]=pb.z; Bs[tb][lcB+3][lrB]=pb.w; }
            __syncthreads();
            s = tb;
        }
    }

#pragma unroll
    for (int i = 0; i < 8; i++) {
        int r = row0 + ty*8 + i;
        if (r < M) {
#pragma unroll
            for (int j = 0; j < 4; j++) {
                int cc = col0 + tx*4 + j;
                if (cc < N) {
                    float v = acc[i][j];
                    if (epi) {
                        v += bias[cc];
                        if (epi == 2) v = (v > 20.f) ? v : log1pf(expf(v));
                    }
                    C[(size_t)r*ldc + cc] = v;
                }
            }
        }
    }
}

// ============================================================================
// gemm_small: 32x64 tile, 64 thr, 4x8 micro (x_proj, N=56)
// ============================================================================
__global__ void __launch_bounds__(64) gemm_small(
    const float* __restrict__ A, int lda,
    const float* __restrict__ B, int ldb,
    float* __restrict__ C, int ldc,
    int M, int N, int K)
{
    __shared__ __align__(16) float As[2][KC][36];
    __shared__ __align__(16) float Bs[2][KC][68];

    const int tid = threadIdx.x;
    const int tx  = tid & 7;
    const int ty  = tid >> 3;
    const int row0 = blockIdx.y * 32;
    const int col0 = blockIdx.x * 64;

    const int lrA = tid >> 1;
    const int lcA = (tid & 1) << 2;
    const int lrB = tid;

    const int ar = row0 + lrA;
    const int br = col0 + lrB;
    const bool aval = (ar < M);
    const bool bval = (br < N);
    const float* Ap = A + (size_t)ar * lda + lcA;
    const float* Bp = B + (size_t)br * ldb;

    float acc[4][8];
#pragma unroll
    for (int i = 0; i < 4; i++)
#pragma unroll
        for (int j = 0; j < 8; j++) acc[i][j] = 0.f;

    const int NC = K / KC;
    float4 pa = make_float4(0.f,0.f,0.f,0.f);
    float4 pb0 = pa, pb1 = pa;
    if (aval) pa = *(const float4*)Ap;
    if (bval) { pb0 = *(const float4*)Bp; pb1 = *(const float4*)(Bp+4); }

    int s = 0;
    As[0][lcA+0][lrA]=pa.x; As[0][lcA+1][lrA]=pa.y; As[0][lcA+2][lrA]=pa.z; As[0][lcA+3][lrA]=pa.w;
    Bs[0][0][lrB]=pb0.x; Bs[0][1][lrB]=pb0.y; Bs[0][2][lrB]=pb0.z; Bs[0][3][lrB]=pb0.w;
    Bs[0][4][lrB]=pb1.x; Bs[0][5][lrB]=pb1.y; Bs[0][6][lrB]=pb1.z; Bs[0][7][lrB]=pb1.w;
    __syncthreads();

    for (int c = 1; c <= NC; ++c) {
        const bool more = (c < NC);
        if (more) {
            pa  = aval ? *(const float4*)(Ap + c*KC) : make_float4(0.f,0.f,0.f,0.f);
            pb0 = bval ? *(const float4*)(Bp + c*KC) : make_float4(0.f,0.f,0.f,0.f);
            pb1 = bval ? *(const float4*)(Bp + c*KC + 4) : make_float4(0.f,0.f,0.f,0.f);
        }
#pragma unroll
        for (int k = 0; k < KC; ++k) {
            float4 a0 = *(const float4*)&As[s][k][ty*4];
            float4 b0 = *(const float4*)&Bs[s][k][tx*8];
            float4 b1 = *(const float4*)&Bs[s][k][tx*8+4];
            float ra[4] = {a0.x,a0.y,a0.z,a0.w};
            float rb[8] = {b0.x,b0.y,b0.z,b0.w,b1.x,b1.y,b1.z,b1.w};
#pragma unroll
            for (int i = 0; i < 4; i++)
#pragma unroll
                for (int j = 0; j < 8; j++)
                    acc[i][j] += ra[i]*rb[j];
        }
        if (more) {
            int tb = s ^ 1;
            As[tb][lcA+0][lrA]=pa.x; As[tb][lcA+1][lrA]=pa.y; As[tb][lcA+2][lrA]=pa.z; As[tb][lcA+3][lrA]=pa.w;
            Bs[tb][0][lrB]=pb0.x; Bs[tb][1][lrB]=pb0.y; Bs[tb][2][lrB]=pb0.z; Bs[tb][3][lrB]=pb0.w;
            Bs[tb][4][lrB]=pb1.x; Bs[tb][5][lrB]=pb1.y; Bs[tb][6][lrB]=pb1.z; Bs[tb][7][lrB]=pb1.w;
            __syncthreads();
            s = tb;
        }
    }

#pragma unroll
    for (int i = 0; i < 4; i++) {
        int r = row0 + ty*4 + i;
        if (r < M) {
#pragma unroll
            for (int j = 0; j < 8; j++) {
                int cc = col0 + tx*8 + j;
                if (cc < N) C[(size_t)r*ldc + cc] = acc[i][j];
            }
        }
    }
}

// ---------------- im2col ----------------
__global__ void im2col_kernel(const float* __restrict__ x) {
    int idx = blockIdx.x * blockDim.x + threadIdx.x;
    if (idx >= MPATCH*KPATCH) return;
    int m = idx / KPATCH, k = idx - m*KPATCH;
    int b = m / NPATCH,  p = m - b*NPATCH;
    int pr = p / 14, pc = p - pr*14;
    int c = k >> 8, r = k & 255;
    int i = r >> 4, j = r & 15;
    g_im2col[idx] = x[(((size_t)b*3 + c)*224 + (pr*16 + i))*224 + pc*16 + j];
}

// ---------------- assemble tokens + pos_embed; zero residual ----------
__global__ void assemble_kernel(const float* __restrict__ cls, const float* __restrict__ pos) {
    int idx = blockIdx.x * blockDim.x + threadIdx.x;
    if (idx >= MTOK*DIM) return;
    int m = idx / DIM, d = idx - m*DIM;
    int b = m / SEQ, t = m - b*SEQ;
    float v = (t == 0) ? cls[d] : g_y[((size_t)b*NPATCH + (t-1))*DIM + d];
    g_hid[idx] = v + pos[t*DIM + d];
    g_res[idx] = 0.f;
}

// ---------------- block reduction (96 threads) ----------------
__device__ __forceinline__ float block_sum_96(float v) {
    __shared__ float sh[3];
#pragma unroll
    for (int o = 16; o > 0; o >>= 1) v += __shfl_down_sync(0xffffffffu, v, o);
    int w = threadIdx.x >> 5, lane = threadIdx.x & 31;
    if (lane == 0) sh[w] = v;
    __syncthreads();
    float r = sh[0] + sh[1] + sh[2];
    __syncthreads();
    return r;
}

// ---------------- residual add + LayerNorm ----------------
__global__ void resln_kernel(const float* __restrict__ nw, const float* __restrict__ nb) {
    int t = blockIdx.x;
    int i = threadIdx.x;
    float4* res4 = (float4*)(g_res + (size_t)t*DIM);
    const float4* hid4 = (const float4*)(g_hid + (size_t)t*DIM);
    float4 v = res4[i];
    float4 h = hid4[i];
    v.x += h.x; v.y += h.y; v.z += h.z; v.w += h.w;
    res4[i] = v;
    float mu = block_sum_96(v.x+v.y+v.z+v.w) * (1.f/DIM);
    float dx=v.x-mu, dy=v.y-mu, dz=v.z-mu, dw=v.w-mu;
    float var = block_sum_96(dx*dx+dy*dy+dz*dz+dw*dw) * (1.f/DIM);
    float rstd = rsqrtf(var + 1e-5f);
    float4 w4 = ((const float4*)nw)[i];
    float4 b4 = ((const float4*)nb)[i];
    float4 o;
    o.x = dx*rstd*w4.x + b4.x;
    o.y = dy*rstd*w4.y + b4.y;
    o.z = dz*rstd*w4.z + b4.z;
    o.w = dw*rstd*w4.w + b4.w;
    ((float4*)(g_u + (size_t)t*DIM))[i] = o;
}

// ---------------- final LN on cls token ----------------
__global__ void finalln_kernel(const float* __restrict__ nw, const float* __restrict__ nb) {
    int b = blockIdx.x;
    int i = threadIdx.x;
    size_t off = (size_t)(b*SEQ)*DIM;
    float4 v = ((const float4*)(g_res + off))[i];
    float4 h = ((const float4*)(g_hid + off))[i];
    v.x += h.x; v.y += h.y; v.z += h.z; v.w += h.w;
    float mu = block_sum_96(v.x+v.y+v.z+v.w) * (1.f/DIM);
    float dx=v.x-mu, dy=v.y-mu, dz=v.z-mu, dw=v.w-mu;
    float var = block_sum_96(dx*dx+dy*dy+dz*dz+dw*dw) * (1.f/DIM);
    float rstd = rsqrtf(var + 1e-5f);
    float4 w4 = ((const float4*)nw)[i];
    float4 b4 = ((const float4*)nb)[i];
    float4 o;
    o.x = dx*rstd*w4.x + b4.x;
    o.y = dy*rstd*w4.y + b4.y;
    o.z = dz*rstd*w4.z + b4.z;
    o.w = dw*rstd*w4.w + b4.w;
    ((float4*)(g_cls + (size_t)b*DIM))[i] = o;
}

// ---------------- depthwise causal conv1d + bias + SiLU --------
__global__ void conv_silu_kernel(const float* __restrict__ wc, const float* __restrict__ bc) {
    int idx = blockIdx.x * blockDim.x + threadIdx.x;
    if (idx >= MTOK*DIN) return;
    int m = idx / DIN, c = idx - m*DIN;
    int b = m / SEQ, l = m - b*SEQ;
    const float* w = wc + c*4;
    float acc = bc[c];
#pragma unroll
    for (int k = 0; k < 4; k++) {
        int ll = l - 3 + k;
        if (ll >= 0) acc += g_xz[((size_t)(b*SEQ + ll))*(2*DIN) + c] * w[k];
    }
    float sg = 1.f / (1.f + __expf(-acc));
    g_xcs[idx] = acc * sg;
}

// ---------------- selective scan + skip + gating --------
__global__ void scan_kernel(const float* __restrict__ Alog, const float* __restrict__ Dssm) {
    int b = blockIdx.y;
    int d = blockIdx.x*128 + threadIdx.x;
    float Av[DST], s[DST];
#pragma unroll
    for (int n = 0; n < DST; n++) { Av[n] = -__expf(Alog[d*DST + n]); s[n] = 0.f; }
    float Dp = Dssm[d];
    __shared__ float sBC[2][32];
    if (threadIdx.x < 32)
        sBC[0][threadIdx.x] = g_dbl[(size_t)(b*SEQ)*56 + DTRANK + threadIdx.x];
    __syncthreads();
    for (int l = 0; l < SEQ; l++) {
        int m = b*SEQ + l;
        int cur = l & 1;
        if (l + 1 < SEQ && threadIdx.x < 32)
            sBC[cur^1][threadIdx.x] = g_dbl[(size_t)(m+1)*56 + DTRANK + threadIdx.x];
        float dt = g_dt[(size_t)m*DIN + d];
        float xv = g_xcs[(size_t)m*DIN + d];
        float zv = g_xz[(size_t)m*(2*DIN) + DIN + d];
        float dtx = dt * xv;
        float y = 0.f;
#pragma unroll
        for (int n = 0; n < DST; n++) {
            s[n] = s[n]*__expf(dt*Av[n]) + dtx*sBC[cur][n];
            y += s[n]*sBC[cur][16+n];
        }
        float sg = 1.f / (1.f + __expf(-zv));
        g_y[(size_t)m*DIN + d] = (y + xv*Dp) * (zv*sg);
        __syncthreads();
    }
}

// ---------------- host launcher ----------------
static inline dim3 tf32_grid(int M, int N) { return dim3(N/128, (M+127)/128); }
static inline dim3 big_grid(int M, int N)  { return dim3((N+63)/64, (M+127)/128); }

extern "C" void kernel_launch(void* const* d_in, const int* in_sizes, int n_in,
                              void* d_out, int out_size)
{
    const float* x          = (const float*)d_in[0];
    const float* patch_w    = (const float*)d_in[1];
    const float* patch_b    = (const float*)d_in[2];
    const float* cls_tok    = (const float*)d_in[3];
    const float* pos_emb    = (const float*)d_in[4];
    const float* in_proj_w  = (const float*)d_in[5];
    const float* conv_w     = (const float*)d_in[6];
    const float* conv_b     = (const float*)d_in[7];
    const float* x_proj_w   = (const float*)d_in[8];
    const float* dt_proj_w  = (const float*)d_in[9];
    const float* dt_proj_b  = (const float*)d_in[10];
    const float* A_log      = (const float*)d_in[11];
    const float* D_ssm      = (const float*)d_in[12];
    const float* out_proj_w = (const float*)d_in[13];
    const float* norm_w     = (const float*)d_in[14];
    const float* norm_b     = (const float*)d_in[15];
    const float* normf_w    = (const float*)d_in[16];
    const float* normf_b    = (const float*)d_in[17];
    const float* head_w     = (const float*)d_in[18];
    const float* head_b     = (const float*)d_in[19];
    float* out = (float*)d_out;

    float *p_im2col, *p_u, *p_xz, *p_xcs, *p_dbl, *p_dt, *p_y, *p_hid, *p_cls;
    cudaGetSymbolAddress((void**)&p_im2col, g_im2col);
    cudaGetSymbolAddress((void**)&p_u,      g_u);
    cudaGetSymbolAddress((void**)&p_xz,     g_xz);
    cudaGetSymbolAddress((void**)&p_xcs,    g_xcs);
    cudaGetSymbolAddress((void**)&p_dbl,    g_dbl);
    cudaGetSymbolAddress((void**)&p_dt,     g_dt);
    cudaGetSymbolAddress((void**)&p_y,      g_y);
    cudaGetSymbolAddress((void**)&p_hid,    g_hid);
    cudaGetSymbolAddress((void**)&p_cls,    g_cls);

    // patch embed: im2col -> TF32 GEMM (+bias) into g_y
    im2col_kernel<<<(MPATCH*KPATCH + 255)/256, 256>>>(x);
    gemm_tf32<<<tf32_grid(MPATCH, DIM), 256>>>(p_im2col, KPATCH, patch_w, KPATCH,
                                               p_y, DIM, patch_b, MPATCH, DIM, KPATCH, 1);
    assemble_kernel<<<(MTOK*DIM + 255)/256, 256>>>(cls_tok, pos_emb);

    for (int L = 0; L < NLAYER; L++) {
        resln_kernel<<<MTOK, 96>>>(norm_w + L*DIM, norm_b + L*DIM);
        // in_proj: (3152 x 384) @ (1536 x 384)^T -> xz  [TF32, 300 CTAs]
        gemm_tf32<<<tf32_grid(MTOK, 2*DIN), 256>>>(p_u, DIM,
            in_proj_w + (size_t)L*2*DIN*DIM, DIM, p_xz, 2*DIN, (const float*)0,
            MTOK, 2*DIN, DIM, 0);
        conv_silu_kernel<<<(MTOK*DIN + 255)/256, 256>>>(conv_w + L*DIN*4, conv_b + L*DIN);
        // x_proj: (3152 x 768) @ (56 x 768)^T -> dbl  [fp32 small]
        gemm_small<<<dim3(1, (MTOK+31)/32), 64>>>(p_xcs, DIN,
            x_proj_w + (size_t)L*56*DIN, DIN, p_dbl, 56, MTOK, 56, DIN);
        // dt_proj: (3152 x 24) @ (768 x 24)^T + bias -> softplus  [fp32]
        gemm_big<<<big_grid(MTOK, DIN), 256>>>(p_dbl, 56,
            dt_proj_w + (size_t)L*DIN*DTRANK, DTRANK, p_dt, DIN,
            dt_proj_b + L*DIN, MTOK, DIN, DTRANK, 2);
        scan_kernel<<<dim3(DIN/128, BATCH), 128>>>(A_log + (size_t)L*DIN*DST, D_ssm + L*DIN);
        // out_proj: (3152 x 768) @ (384 x 768)^T -> hid  [TF32, 75 CTAs]
        gemm_tf32<<<tf32_grid(MTOK, DIM), 256>>>(p_y, DIN,
            out_proj_w + (size_t)L*DIM*DIN, DIN, p_hid, DIM, (const float*)0,
            MTOK, DIM, DIN, 0);
    }

    finalln_kernel<<<BATCH, 96>>>(normf_w, normf_b);
    gemm_big<<<big_grid(BATCH, NCLS), 256>>>(p_cls, DIM, head_w, DIM,
                                             out, NCLS, head_b, BATCH, NCLS, DIM, 1);
}